// round 11
// baseline (speedup 1.0000x reference)
#include <cuda_runtime.h>
#include <math.h>
#include <stdint.h>

#define N_NODES 50000
#define N_EDGES 800000
#define D 256
#define NG 512
#define NC 10
#define LN_EPS 1e-5f

#define SCAN_BLK 512
#define SCAN_NB ((N_NODES + SCAN_BLK - 1) / SCAN_BLK)   // 98

// ---------------- scratch (device globals; no allocation allowed) -------------
__device__ float g_A[N_NODES * D];       // GEMM output (fp32)
__device__ float g_h[N_NODES * D];       // tf32-hi operand
__device__ float g_l[N_NODES * D];       // tf32-lo operand
__device__ float g_B[N_NODES * D];       // final activations (fp32)
__device__ float g_w1h[D * D], g_w1l[D * D];   // W1^T split
__device__ float g_w2h[D * D], g_w2l[D * D];   // W2^T split
__device__ float g_dinv[N_NODES];
__device__ int   g_counts[N_NODES];
__device__ int   g_offsets[N_NODES + 1];
__device__ int   g_cursor[N_NODES];
__device__ int   g_bsums[SCAN_NB];
__device__ int   g_csr_src[N_EDGES];
__device__ float g_csr_w[N_EDGES];

// ---------------- helpers ----------------
__device__ __forceinline__ float to_tf32(float x) {
    uint32_t u;
    asm("cvt.rna.tf32.f32 %0, %1;" : "=r"(u) : "f"(x));
    return __uint_as_float(u);
}

#define MMA_TF32(d, a, b0, b1)                                              \
    asm volatile(                                                           \
        "mma.sync.aligned.m16n8k8.row.col.f32.tf32.tf32.f32 "               \
        "{%0,%1,%2,%3}, {%4,%5,%6,%7}, {%8,%9}, {%0,%1,%2,%3};"             \
        : "+f"((d)[0]), "+f"((d)[1]), "+f"((d)[2]), "+f"((d)[3])            \
        : "r"((a)[0]), "r"((a)[1]), "r"((a)[2]), "r"((a)[3]),               \
          "r"(b0), "r"(b1))

// ---------------- prep kernels ----------------
__global__ void prep_x_kernel(const float* __restrict__ x,
                              float* __restrict__ xh, float* __restrict__ xl) {
    int i = blockIdx.x * blockDim.x + threadIdx.x;
    if (i < N_NODES * (D / 4)) {
        float4 v = ((const float4*)x)[i];
        float4 h, l;
        h.x = to_tf32(v.x); l.x = to_tf32(v.x - h.x);
        h.y = to_tf32(v.y); l.y = to_tf32(v.y - h.y);
        h.z = to_tf32(v.z); l.z = to_tf32(v.z - h.z);
        h.w = to_tf32(v.w); l.w = to_tf32(v.w - h.w);
        ((float4*)xh)[i] = h;
        ((float4*)xl)[i] = l;
    }
}

// transpose + split: Wt[n][k] = W[k][n]
__global__ void prep_w_kernel(const float* __restrict__ W,
                              float* __restrict__ Wth, float* __restrict__ Wtl) {
    int n = blockIdx.x;
    int k = threadIdx.x;
    float v = W[k * D + n];
    float h = to_tf32(v);
    Wth[n * D + k] = h;
    Wtl[n * D + k] = to_tf32(v - h);
}

// ---------------- degree / CSR ----------------
__global__ void count_zero_kernel(int* counts) {
    int i = blockIdx.x * blockDim.x + threadIdx.x;
    if (i < N_NODES) counts[i] = 0;
}

__global__ void deg_count_kernel(const int* __restrict__ dst, int* counts) {
    int e = blockIdx.x * blockDim.x + threadIdx.x;
    if (e < N_EDGES) atomicAdd(&counts[dst[e]], 1);
}

__global__ void scan_blocksum_kernel(const int* __restrict__ counts, int* __restrict__ bsums) {
    int t = threadIdx.x;
    int i = blockIdx.x * SCAN_BLK + t;
    int v = (i < N_NODES) ? counts[i] : 0;
#pragma unroll
    for (int o = 16; o > 0; o >>= 1) v += __shfl_xor_sync(0xffffffffu, v, o);
    __shared__ int ws[SCAN_BLK / 32];
    if ((t & 31) == 0) ws[t >> 5] = v;
    __syncthreads();
    if (t == 0) {
        int s = 0;
#pragma unroll
        for (int w = 0; w < SCAN_BLK / 32; w++) s += ws[w];
        bsums[blockIdx.x] = s;
    }
}

__global__ void scan_sums_kernel(int* bsums) {
    int t = threadIdx.x;
    int lane = t & 31, w = t >> 5;
    int v = (t < SCAN_NB) ? bsums[t] : 0;
    int inc = v;
#pragma unroll
    for (int o = 1; o < 32; o <<= 1) {
        int n = __shfl_up_sync(0xffffffffu, inc, o);
        if (lane >= o) inc += n;
    }
    __shared__ int ws[4];
    if (lane == 31) ws[w] = inc;
    __syncthreads();
    int add = 0;
    for (int k = 0; k < w; k++) add += ws[k];
    if (t < SCAN_NB) bsums[t] = inc - v + add;
}

__global__ void scan_local_kernel(const int* __restrict__ counts,
                                  const int* __restrict__ bsums,
                                  int* __restrict__ offsets,
                                  int* __restrict__ cursor,
                                  float* __restrict__ dinv) {
    int t = threadIdx.x;
    int lane = t & 31, w = t >> 5;
    int i = blockIdx.x * SCAN_BLK + t;
    int v = (i < N_NODES) ? counts[i] : 0;
    int inc = v;
#pragma unroll
    for (int o = 1; o < 32; o <<= 1) {
        int n = __shfl_up_sync(0xffffffffu, inc, o);
        if (lane >= o) inc += n;
    }
    __shared__ int ws[SCAN_BLK / 32];
    if (lane == 31) ws[w] = inc;
    __syncthreads();
    int add = bsums[blockIdx.x];
    for (int k = 0; k < w; k++) add += ws[k];
    int excl = inc - v + add;
    if (i < N_NODES) {
        offsets[i] = excl;
        cursor[i] = excl;
        dinv[i] = rsqrtf((float)(v + 1));
        if (i == N_NODES - 1) offsets[N_NODES] = excl + v;
    }
}

__global__ void fill_kernel(const int* __restrict__ src, const int* __restrict__ dst,
                            const float* __restrict__ dinv,
                            int* cursor, int* __restrict__ csr_src, float* __restrict__ csr_w) {
    int e = blockIdx.x * blockDim.x + threadIdx.x;
    if (e < N_EDGES) {
        int s = src[e], d = dst[e];
        int pos = atomicAdd(&cursor[d], 1);
        csr_src[pos] = s;
        csr_w[pos] = dinv[s] * dinv[d];
    }
}

// ---------------- mma.sync 3xTF32 GEMM: C[M,256] = A @ W (Wt[n][k] operands) ---
// CTA 128x128, 8 warps (warp tile 32x64), K chunks of 32.
#define KC 32
#define NCHUNK (D / KC)         // 8
#define SSTR 36                 // smem row stride (floats), conflict-free
#define TILE_F (128 * SSTR)
#define GEMM_SMEM (4 * TILE_F * 4)   // bytes = 73728

__global__ __launch_bounds__(256)
void gemm_mma_kernel(const float* __restrict__ Ah, const float* __restrict__ Al,
                     const float* __restrict__ Bh, const float* __restrict__ Bl,
                     float* __restrict__ C) {
    extern __shared__ float sm[];
    float* sAh = sm;
    float* sAl = sm + TILE_F;
    float* sBh = sm + 2 * TILE_F;
    float* sBl = sm + 3 * TILE_F;

    int tid = threadIdx.x;
    int lane = tid & 31;
    int w = tid >> 5;
    int bm = blockIdx.y * 128;
    int bn = blockIdx.x * 128;
    int wm = (w & 3) * 32;       // warp m-offset in tile
    int wn = (w >> 2) * 64;      // warp n-offset in tile
    int gid = lane >> 2;         // 0..7
    int tig = lane & 3;          // 0..3

    const float4* Ah4 = (const float4*)Ah;
    const float4* Al4 = (const float4*)Al;
    const float4* Bh4 = (const float4*)Bh;
    const float4* Bl4 = (const float4*)Bl;

    float acc[2][8][4];
#pragma unroll
    for (int mt = 0; mt < 2; mt++)
#pragma unroll
        for (int nt = 0; nt < 8; nt++)
#pragma unroll
            for (int i = 0; i < 4; i++) acc[mt][nt][i] = 0.0f;

    for (int c = 0; c < NCHUNK; c++) {
        // fill smem: 4 tiles of 128 rows x 32 floats each
#pragma unroll
        for (int t = 0; t < 4; t++) {
            int idx = tid + t * 256;       // 0..1023
            int row = idx >> 3;            // 0..127
            int f4  = idx & 7;             // 0..7
            int so = row * SSTR + f4 * 4;
            int ar = bm + row;
            float4 vh = make_float4(0.f, 0.f, 0.f, 0.f);
            float4 vl = make_float4(0.f, 0.f, 0.f, 0.f);
            if (ar < N_NODES) {
                size_t gi = (size_t)ar * (D / 4) + c * 8 + f4;
                vh = Ah4[gi];
                vl = Al4[gi];
            }
            *(float4*)(sAh + so) = vh;
            *(float4*)(sAl + so) = vl;
            size_t wi = (size_t)(bn + row) * (D / 4) + c * 8 + f4;
            *(float4*)(sBh + so) = Bh4[wi];
            *(float4*)(sBl + so) = Bl4[wi];
        }
        __syncthreads();

#pragma unroll
        for (int ks = 0; ks < 4; ks++) {
            int kb = ks * 8 + tig;
            // A fragments for 2 m-tiles (hi and lo)
            uint32_t fah[2][4], fal[2][4];
#pragma unroll
            for (int mt = 0; mt < 2; mt++) {
                int m0 = wm + mt * 16 + gid;
                fah[mt][0] = __float_as_uint(sAh[m0 * SSTR + kb]);
                fah[mt][1] = __float_as_uint(sAh[(m0 + 8) * SSTR + kb]);
                fah[mt][2] = __float_as_uint(sAh[m0 * SSTR + kb + 4]);
                fah[mt][3] = __float_as_uint(sAh[(m0 + 8) * SSTR + kb + 4]);
                fal[mt][0] = __float_as_uint(sAl[m0 * SSTR + kb]);
                fal[mt][1] = __float_as_uint(sAl[(m0 + 8) * SSTR + kb]);
                fal[mt][2] = __float_as_uint(sAl[m0 * SSTR + kb + 4]);
                fal[mt][3] = __float_as_uint(sAl[(m0 + 8) * SSTR + kb + 4]);
            }
#pragma unroll
            for (int nt = 0; nt < 8; nt++) {
                int n0 = wn + nt * 8 + gid;
                uint32_t bh0 = __float_as_uint(sBh[n0 * SSTR + kb]);
                uint32_t bh1 = __float_as_uint(sBh[n0 * SSTR + kb + 4]);
                uint32_t bl0 = __float_as_uint(sBl[n0 * SSTR + kb]);
                uint32_t bl1 = __float_as_uint(sBl[n0 * SSTR + kb + 4]);
#pragma unroll
                for (int mt = 0; mt < 2; mt++) {
                    MMA_TF32(acc[mt][nt], fah[mt], bh0, bh1);
                    MMA_TF32(acc[mt][nt], fal[mt], bh0, bh1);
                    MMA_TF32(acc[mt][nt], fah[mt], bl0, bl1);
                }
            }
        }
        __syncthreads();
    }

    // epilogue: each thread owns (row gid, gid+8) x (col 2*tig, +1) per 16x8 tile
#pragma unroll
    for (int mt = 0; mt < 2; mt++) {
        int r0 = bm + wm + mt * 16 + gid;
        int r1 = r0 + 8;
#pragma unroll
        for (int nt = 0; nt < 8; nt++) {
            int col = bn + wn + nt * 8 + 2 * tig;
            if (r0 < N_NODES)
                *(float2*)(C + (size_t)r0 * D + col) =
                    make_float2(acc[mt][nt][0], acc[mt][nt][1]);
            if (r1 < N_NODES)
                *(float2*)(C + (size_t)r1 * D + col) =
                    make_float2(acc[mt][nt][2], acc[mt][nt][3]);
        }
    }
}

// ---------------- fused CSR aggregation + bias + LayerNorm + ReLU ----------------
template <bool SPLIT>
__global__ void agg_ln_kernel(const float* __restrict__ h,
                              const int* __restrict__ offsets,
                              const int* __restrict__ csr_src,
                              const float* __restrict__ csr_w,
                              const float* __restrict__ dinv,
                              const float* __restrict__ bias,
                              const float* __restrict__ lw,
                              const float* __restrict__ lb,
                              float* __restrict__ out_h,
                              float* __restrict__ out_l) {
    int row = blockIdx.x * 8 + (threadIdx.x >> 5);
    int lane = threadIdx.x & 31;
    if (row >= N_NODES) return;

    float di = dinv[row];
    float sw = di * di;
    const float4* hp = (const float4*)(h + (size_t)row * D);
    float4 s0 = hp[lane], s1 = hp[lane + 32];
    float4 v0 = make_float4(s0.x * sw, s0.y * sw, s0.z * sw, s0.w * sw);
    float4 v1 = make_float4(s1.x * sw, s1.y * sw, s1.z * sw, s1.w * sw);

    int e0 = offsets[row];
    int e1 = offsets[row + 1];
    int e = e0;
    for (; e + 2 <= e1; e += 2) {
        int  sA = csr_src[e],   sB = csr_src[e + 1];
        float wA = csr_w[e],    wB = csr_w[e + 1];
        const float4* pA = (const float4*)(h + (size_t)sA * D);
        const float4* pB = (const float4*)(h + (size_t)sB * D);
        float4 a0 = pA[lane], a1 = pA[lane + 32];
        float4 b0 = pB[lane], b1 = pB[lane + 32];
        v0.x += a0.x * wA; v0.y += a0.y * wA; v0.z += a0.z * wA; v0.w += a0.w * wA;
        v1.x += a1.x * wA; v1.y += a1.y * wA; v1.z += a1.z * wA; v1.w += a1.w * wA;
        v0.x += b0.x * wB; v0.y += b0.y * wB; v0.z += b0.z * wB; v0.w += b0.w * wB;
        v1.x += b1.x * wB; v1.y += b1.y * wB; v1.z += b1.z * wB; v1.w += b1.w * wB;
    }
    if (e < e1) {
        int  sA = csr_src[e];
        float wA = csr_w[e];
        const float4* pA = (const float4*)(h + (size_t)sA * D);
        float4 a0 = pA[lane], a1 = pA[lane + 32];
        v0.x += a0.x * wA; v0.y += a0.y * wA; v0.z += a0.z * wA; v0.w += a0.w * wA;
        v1.x += a1.x * wA; v1.y += a1.y * wA; v1.z += a1.z * wA; v1.w += a1.w * wA;
    }

    const float4* bp = (const float4*)bias;
    float4 b0 = bp[lane], b1 = bp[lane + 32];
    v0.x += b0.x; v0.y += b0.y; v0.z += b0.z; v0.w += b0.w;
    v1.x += b1.x; v1.y += b1.y; v1.z += b1.z; v1.w += b1.w;

    float s = v0.x + v0.y + v0.z + v0.w + v1.x + v1.y + v1.z + v1.w;
#pragma unroll
    for (int o = 16; o > 0; o >>= 1) s += __shfl_xor_sync(0xffffffffu, s, o);
    float mu = s * (1.0f / D);

    v0.x -= mu; v0.y -= mu; v0.z -= mu; v0.w -= mu;
    v1.x -= mu; v1.y -= mu; v1.z -= mu; v1.w -= mu;
    float q = v0.x*v0.x + v0.y*v0.y + v0.z*v0.z + v0.w*v0.w
            + v1.x*v1.x + v1.y*v1.y + v1.z*v1.z + v1.w*v1.w;
#pragma unroll
    for (int o = 16; o > 0; o >>= 1) q += __shfl_xor_sync(0xffffffffu, q, o);
    float inv = rsqrtf(q * (1.0f / D) + LN_EPS);

    const float4* wp = (const float4*)lw;
    const float4* lp = (const float4*)lb;
    float4 w0 = wp[lane], w1 = wp[lane + 32];
    float4 l0 = lp[lane], l1 = lp[lane + 32];

    float4 o0, o1;
    o0.x = fmaxf(v0.x * inv * w0.x + l0.x, 0.f);
    o0.y = fmaxf(v0.y * inv * w0.y + l0.y, 0.f);
    o0.z = fmaxf(v0.z * inv * w0.z + l0.z, 0.f);
    o0.w = fmaxf(v0.w * inv * w0.w + l0.w, 0.f);
    o1.x = fmaxf(v1.x * inv * w1.x + l1.x, 0.f);
    o1.y = fmaxf(v1.y * inv * w1.y + l1.y, 0.f);
    o1.z = fmaxf(v1.z * inv * w1.z + l1.z, 0.f);
    o1.w = fmaxf(v1.w * inv * w1.w + l1.w, 0.f);

    if (SPLIT) {
        float4 hh0, hh1, ll0, ll1;
        hh0.x = to_tf32(o0.x); ll0.x = to_tf32(o0.x - hh0.x);
        hh0.y = to_tf32(o0.y); ll0.y = to_tf32(o0.y - hh0.y);
        hh0.z = to_tf32(o0.z); ll0.z = to_tf32(o0.z - hh0.z);
        hh0.w = to_tf32(o0.w); ll0.w = to_tf32(o0.w - hh0.w);
        hh1.x = to_tf32(o1.x); ll1.x = to_tf32(o1.x - hh1.x);
        hh1.y = to_tf32(o1.y); ll1.y = to_tf32(o1.y - hh1.y);
        hh1.z = to_tf32(o1.z); ll1.z = to_tf32(o1.z - hh1.z);
        hh1.w = to_tf32(o1.w); ll1.w = to_tf32(o1.w - hh1.w);
        float4* oh = (float4*)(out_h + (size_t)row * D);
        float4* ol = (float4*)(out_l + (size_t)row * D);
        oh[lane] = hh0; oh[lane + 32] = hh1;
        ol[lane] = ll0; ol[lane + 32] = ll1;
    } else {
        float4* op = (float4*)(out_h + (size_t)row * D);
        op[lane] = o0;
        op[lane + 32] = o1;
    }
}

// ---------------- fused pool + head (batch is sorted) ----------------
__device__ __forceinline__ int lower_bound_dev(const int* a, int n, int key) {
    int lo = 0, hi = n;
    while (lo < hi) {
        int mid = (lo + hi) >> 1;
        if (a[mid] < key) lo = mid + 1; else hi = mid;
    }
    return lo;
}

__global__ void pool_head_kernel(const int* __restrict__ batch,
                                 const float* __restrict__ h,
                                 const float* __restrict__ linW,
                                 const float* __restrict__ linb,
                                 float* __restrict__ out) {
    __shared__ float row[D];
    __shared__ int s_start, s_end;
    int g = blockIdx.x;
    int c = threadIdx.x;
    if (c == 0) {
        s_start = lower_bound_dev(batch, N_NODES, g);
        s_end   = lower_bound_dev(batch, N_NODES, g + 1);
    }
    __syncthreads();
    int start = s_start, end = s_end;
    float sum = 0.0f;
    for (int n = start; n < end; n++) sum += h[(size_t)n * D + c];
    float cnt = (float)(end - start);
    row[c] = sum / fmaxf(cnt, 1.0f);
    __syncthreads();
    if (c < NC) {
        float acc = linb[c];
#pragma unroll 8
        for (int k = 0; k < D; k++) acc += row[k] * linW[k * NC + c];
        out[g * NC + c] = acc;
    }
}

// ---------------- launch ----------------
extern "C" void kernel_launch(void* const* d_in, const int* in_sizes, int n_in,
                              void* d_out, int out_size) {
    const float* x     = (const float*)d_in[0];
    const int*   ei    = (const int*)d_in[1];
    const int*   batch = (const int*)d_in[2];
    const float* W1    = (const float*)d_in[3];
    const float* b1    = (const float*)d_in[4];
    const float* W2    = (const float*)d_in[5];
    const float* b2    = (const float*)d_in[6];
    const float* ln1w  = (const float*)d_in[7];
    const float* ln1b  = (const float*)d_in[8];
    const float* ln2w  = (const float*)d_in[9];
    const float* ln2b  = (const float*)d_in[10];
    const float* linW  = (const float*)d_in[11];
    const float* linb  = (const float*)d_in[12];
    float* out = (float*)d_out;

    const int* src = ei;
    const int* dst = ei + N_EDGES;

    float *A, *H, *L, *B, *w1h, *w1l, *w2h, *w2l, *dinv, *csr_w;
    int *counts, *offsets, *cursor, *csr_src, *bsums;
    cudaGetSymbolAddress((void**)&A,       g_A);
    cudaGetSymbolAddress((void**)&H,       g_h);
    cudaGetSymbolAddress((void**)&L,       g_l);
    cudaGetSymbolAddress((void**)&B,       g_B);
    cudaGetSymbolAddress((void**)&w1h,     g_w1h);
    cudaGetSymbolAddress((void**)&w1l,     g_w1l);
    cudaGetSymbolAddress((void**)&w2h,     g_w2h);
    cudaGetSymbolAddress((void**)&w2l,     g_w2l);
    cudaGetSymbolAddress((void**)&dinv,    g_dinv);
    cudaGetSymbolAddress((void**)&counts,  g_counts);
    cudaGetSymbolAddress((void**)&offsets, g_offsets);
    cudaGetSymbolAddress((void**)&cursor,  g_cursor);
    cudaGetSymbolAddress((void**)&bsums,   g_bsums);
    cudaGetSymbolAddress((void**)&csr_src, g_csr_src);
    cudaGetSymbolAddress((void**)&csr_w,   g_csr_w);

    cudaFuncSetAttribute(gemm_mma_kernel,
                         cudaFuncAttributeMaxDynamicSharedMemorySize, GEMM_SMEM);

    // prep: operand splits
    prep_x_kernel<<<(N_NODES * (D / 4) + 255) / 256, 256>>>(x, H, L);
    prep_w_kernel<<<D, D>>>(W1, w1h, w1l);
    prep_w_kernel<<<D, D>>>(W2, w2h, w2l);

    // CSR build
    count_zero_kernel<<<(N_NODES + 255) / 256, 256>>>(counts);
    deg_count_kernel<<<(N_EDGES + 255) / 256, 256>>>(dst, counts);
    scan_blocksum_kernel<<<SCAN_NB, SCAN_BLK>>>(counts, bsums);
    scan_sums_kernel<<<1, 128>>>(bsums);
    scan_local_kernel<<<SCAN_NB, SCAN_BLK>>>(counts, bsums, offsets, cursor, dinv);
    fill_kernel<<<(N_EDGES + 255) / 256, 256>>>(src, dst, dinv, cursor, csr_src, csr_w);

    dim3 ggrid(2, (N_NODES + 127) / 128);

    // layer 1
    gemm_mma_kernel<<<ggrid, 256, GEMM_SMEM>>>(H, L, w1h, w1l, A);
    agg_ln_kernel<true><<<(N_NODES + 7) / 8, 256>>>(A, offsets, csr_src, csr_w, dinv,
                                                    b1, ln1w, ln1b, H, L);
    // layer 2
    gemm_mma_kernel<<<ggrid, 256, GEMM_SMEM>>>(H, L, w2h, w2l, A);
    agg_ln_kernel<false><<<(N_NODES + 7) / 8, 256>>>(A, offsets, csr_src, csr_w, dinv,
                                                     b2, ln2w, ln2b, B, nullptr);

    // pool + head
    pool_head_kernel<<<NG, D>>>(batch, B, linW, linb, out);
}

// round 12
// speedup vs baseline: 1.7998x; 1.7998x over previous
#include <cuda_runtime.h>
#include <cuda_bf16.h>
#include <math.h>
#include <stdint.h>

#define N_NODES 50000
#define N_EDGES 800000
#define D 256
#define NG 512
#define NC 10
#define LN_EPS 1e-5f

#define SCAN_BLK 512
#define SCAN_NB ((N_NODES + SCAN_BLK - 1) / SCAN_BLK)   // 98

// ---------------- scratch (device globals; no allocation allowed) -------------
__device__ __align__(16) float g_A[N_NODES * D];             // GEMM output (fp32)
__device__ __align__(16) float g_B[N_NODES * D];             // final activations
__device__ __align__(16) __nv_bfloat16 g_xh[N_NODES * D];    // bf16-hi operand
__device__ __align__(16) __nv_bfloat16 g_xl[N_NODES * D];    // bf16-lo operand
__device__ __align__(16) __nv_bfloat16 g_w1h[D * D], g_w1l[D * D];  // W1^T split
__device__ __align__(16) __nv_bfloat16 g_w2h[D * D], g_w2l[D * D];  // W2^T split
__device__ float g_dinv[N_NODES];
__device__ int   g_counts[N_NODES];
__device__ int   g_offsets[N_NODES + 1];
__device__ int   g_cursor[N_NODES];
__device__ int   g_bsums[SCAN_NB];
__device__ int   g_csr_src[N_EDGES];
__device__ float g_csr_w[N_EDGES];

// ---------------- helpers ----------------
__device__ __forceinline__ uint32_t sw128(uint32_t off) {
    return off ^ ((off >> 3) & 0x70);
}

__device__ __forceinline__ void split_bf(float v, __nv_bfloat16& h, __nv_bfloat16& l) {
    h = __float2bfloat16(v);
    l = __float2bfloat16(v - __bfloat162float(h));
}

#define MMA_BF16(d, a, b0, b1)                                              \
    asm volatile(                                                           \
        "mma.sync.aligned.m16n8k16.row.col.f32.bf16.bf16.f32 "              \
        "{%0,%1,%2,%3}, {%4,%5,%6,%7}, {%8,%9}, {%0,%1,%2,%3};"             \
        : "+f"((d)[0]), "+f"((d)[1]), "+f"((d)[2]), "+f"((d)[3])            \
        : "r"((a)[0]), "r"((a)[1]), "r"((a)[2]), "r"((a)[3]),               \
          "r"(b0), "r"(b1))

// ---------------- prep kernels ----------------
__global__ void prep_x_kernel(const float* __restrict__ x,
                              __nv_bfloat16* __restrict__ xh,
                              __nv_bfloat16* __restrict__ xl) {
    int i = blockIdx.x * blockDim.x + threadIdx.x;
    if (i < N_NODES * (D / 4)) {
        float4 v = ((const float4*)x)[i];
        __nv_bfloat16 h0, h1, h2, h3, l0, l1, l2, l3;
        split_bf(v.x, h0, l0);
        split_bf(v.y, h1, l1);
        split_bf(v.z, h2, l2);
        split_bf(v.w, h3, l3);
        __nv_bfloat162* xh2 = (__nv_bfloat162*)xh;
        __nv_bfloat162* xl2 = (__nv_bfloat162*)xl;
        xh2[2 * i]     = __nv_bfloat162(h0, h1);
        xh2[2 * i + 1] = __nv_bfloat162(h2, h3);
        xl2[2 * i]     = __nv_bfloat162(l0, l1);
        xl2[2 * i + 1] = __nv_bfloat162(l2, l3);
    }
}

// transpose + split: Wt[n][k] = W[k][n]
__global__ void prep_w_kernel(const float* __restrict__ W,
                              __nv_bfloat16* __restrict__ Wth,
                              __nv_bfloat16* __restrict__ Wtl) {
    int n = blockIdx.x;
    int k = threadIdx.x;
    float v = W[k * D + n];
    __nv_bfloat16 h, l;
    split_bf(v, h, l);
    Wth[n * D + k] = h;
    Wtl[n * D + k] = l;
}

// ---------------- degree / CSR ----------------
__global__ void count_zero_kernel(int* counts) {
    int i = blockIdx.x * blockDim.x + threadIdx.x;
    if (i < N_NODES) counts[i] = 0;
}

__global__ void deg_count_kernel(const int* __restrict__ dst, int* counts) {
    int e = blockIdx.x * blockDim.x + threadIdx.x;
    if (e < N_EDGES) atomicAdd(&counts[dst[e]], 1);
}

__global__ void scan_blocksum_kernel(const int* __restrict__ counts, int* __restrict__ bsums) {
    int t = threadIdx.x;
    int i = blockIdx.x * SCAN_BLK + t;
    int v = (i < N_NODES) ? counts[i] : 0;
#pragma unroll
    for (int o = 16; o > 0; o >>= 1) v += __shfl_xor_sync(0xffffffffu, v, o);
    __shared__ int ws[SCAN_BLK / 32];
    if ((t & 31) == 0) ws[t >> 5] = v;
    __syncthreads();
    if (t == 0) {
        int s = 0;
#pragma unroll
        for (int w = 0; w < SCAN_BLK / 32; w++) s += ws[w];
        bsums[blockIdx.x] = s;
    }
}

__global__ void scan_sums_kernel(int* bsums) {
    int t = threadIdx.x;
    int lane = t & 31, w = t >> 5;
    int v = (t < SCAN_NB) ? bsums[t] : 0;
    int inc = v;
#pragma unroll
    for (int o = 1; o < 32; o <<= 1) {
        int n = __shfl_up_sync(0xffffffffu, inc, o);
        if (lane >= o) inc += n;
    }
    __shared__ int ws[4];
    if (lane == 31) ws[w] = inc;
    __syncthreads();
    int add = 0;
    for (int k = 0; k < w; k++) add += ws[k];
    if (t < SCAN_NB) bsums[t] = inc - v + add;
}

__global__ void scan_local_kernel(const int* __restrict__ counts,
                                  const int* __restrict__ bsums,
                                  int* __restrict__ offsets,
                                  int* __restrict__ cursor,
                                  float* __restrict__ dinv) {
    int t = threadIdx.x;
    int lane = t & 31, w = t >> 5;
    int i = blockIdx.x * SCAN_BLK + t;
    int v = (i < N_NODES) ? counts[i] : 0;
    int inc = v;
#pragma unroll
    for (int o = 1; o < 32; o <<= 1) {
        int n = __shfl_up_sync(0xffffffffu, inc, o);
        if (lane >= o) inc += n;
    }
    __shared__ int ws[SCAN_BLK / 32];
    if (lane == 31) ws[w] = inc;
    __syncthreads();
    int add = bsums[blockIdx.x];
    for (int k = 0; k < w; k++) add += ws[k];
    int excl = inc - v + add;
    if (i < N_NODES) {
        offsets[i] = excl;
        cursor[i] = excl;
        dinv[i] = rsqrtf((float)(v + 1));
        if (i == N_NODES - 1) offsets[N_NODES] = excl + v;
    }
}

__global__ void fill_kernel(const int* __restrict__ src, const int* __restrict__ dst,
                            const float* __restrict__ dinv,
                            int* cursor, int* __restrict__ csr_src, float* __restrict__ csr_w) {
    int e = blockIdx.x * blockDim.x + threadIdx.x;
    if (e < N_EDGES) {
        int s = src[e], d = dst[e];
        int pos = atomicAdd(&cursor[d], 1);
        csr_src[pos] = s;
        csr_w[pos] = dinv[s] * dinv[d];
    }
}

// ------- bf16 mma.sync 3-pass GEMM: C[M,256] = A @ W  (Wt[n][k] operands) -----
// CTA tile 128x128, 8 warps (warp tile 32x64), K chunks of 64, sw128 smem.
#define KC 64
#define NKCH (D / KC)            // 4
#define TILEB (128 * 128)        // bytes per operand tile (128 rows x 64 bf16)
#define GEMM_SMEM (4 * TILEB)    // 65536

__global__ __launch_bounds__(256, 2)
void gemm_bf16_kernel(const __nv_bfloat16* __restrict__ Ah,
                      const __nv_bfloat16* __restrict__ Al,
                      const __nv_bfloat16* __restrict__ Bh,
                      const __nv_bfloat16* __restrict__ Bl,
                      float* __restrict__ C) {
    extern __shared__ char smc[];
    char* sAh = smc;
    char* sAl = smc + TILEB;
    char* sBh = smc + 2 * TILEB;
    char* sBl = smc + 3 * TILEB;

    int tid = threadIdx.x;
    int lane = tid & 31;
    int w = tid >> 5;
    int bm = blockIdx.y * 128;
    int bn = blockIdx.x * 128;
    int wm = (w & 3) * 32;
    int wn = (w >> 2) * 64;
    int gid = lane >> 2;         // 0..7
    int tig = lane & 3;          // 0..3

    float acc[2][8][4];
#pragma unroll
    for (int mt = 0; mt < 2; mt++)
#pragma unroll
        for (int nt = 0; nt < 8; nt++)
#pragma unroll
            for (int i = 0; i < 4; i++) acc[mt][nt][i] = 0.0f;

    for (int c = 0; c < NKCH; c++) {
        // global -> smem: each thread moves 4 float4 per tile (8 bf16 each)
#pragma unroll
        for (int t = 0; t < 4; t++) {
            int idx = tid + t * 256;       // 0..1023
            int row = idx >> 3;            // 0..127
            int f4  = idx & 7;             // 0..7 (16B slots in 128B row)
            uint32_t so = sw128((uint32_t)(row * 128 + f4 * 16));
            int ar = bm + row;
            float4 vh = make_float4(0.f, 0.f, 0.f, 0.f);
            float4 vl = make_float4(0.f, 0.f, 0.f, 0.f);
            if (ar < N_NODES) {
                size_t gi = (size_t)ar * 32 + c * 8 + f4;   // float4 units of 256-bf16 row
                vh = ((const float4*)Ah)[gi];
                vl = ((const float4*)Al)[gi];
            }
            *(float4*)(sAh + so) = vh;
            *(float4*)(sAl + so) = vl;
            size_t wi = (size_t)(bn + row) * 32 + c * 8 + f4;
            *(float4*)(sBh + so) = ((const float4*)Bh)[wi];
            *(float4*)(sBl + so) = ((const float4*)Bl)[wi];
        }
        __syncthreads();

#pragma unroll
        for (int ks = 0; ks < 4; ks++) {
            int kb = ks * 32 + tig * 4;    // byte offset of this thread's k-pair
            uint32_t ah[2][4], al[2][4];
#pragma unroll
            for (int mt = 0; mt < 2; mt++) {
                int m0 = wm + mt * 16 + gid;
                ah[mt][0] = *(const uint32_t*)(sAh + sw128((uint32_t)(m0 * 128 + kb)));
                ah[mt][1] = *(const uint32_t*)(sAh + sw128((uint32_t)((m0 + 8) * 128 + kb)));
                ah[mt][2] = *(const uint32_t*)(sAh + sw128((uint32_t)(m0 * 128 + kb + 16)));
                ah[mt][3] = *(const uint32_t*)(sAh + sw128((uint32_t)((m0 + 8) * 128 + kb + 16)));
                al[mt][0] = *(const uint32_t*)(sAl + sw128((uint32_t)(m0 * 128 + kb)));
                al[mt][1] = *(const uint32_t*)(sAl + sw128((uint32_t)((m0 + 8) * 128 + kb)));
                al[mt][2] = *(const uint32_t*)(sAl + sw128((uint32_t)(m0 * 128 + kb + 16)));
                al[mt][3] = *(const uint32_t*)(sAl + sw128((uint32_t)((m0 + 8) * 128 + kb + 16)));
            }
#pragma unroll
            for (int nt = 0; nt < 8; nt++) {
                int n0 = wn + nt * 8 + gid;
                uint32_t bh0 = *(const uint32_t*)(sBh + sw128((uint32_t)(n0 * 128 + kb)));
                uint32_t bh1 = *(const uint32_t*)(sBh + sw128((uint32_t)(n0 * 128 + kb + 16)));
                uint32_t bl0 = *(const uint32_t*)(sBl + sw128((uint32_t)(n0 * 128 + kb)));
                uint32_t bl1 = *(const uint32_t*)(sBl + sw128((uint32_t)(n0 * 128 + kb + 16)));
#pragma unroll
                for (int mt = 0; mt < 2; mt++) {
                    MMA_BF16(acc[mt][nt], ah[mt], bh0, bh1);
                    MMA_BF16(acc[mt][nt], al[mt], bh0, bh1);
                    MMA_BF16(acc[mt][nt], ah[mt], bl0, bl1);
                }
            }
        }
        __syncthreads();
    }

    // epilogue: thread owns rows (gid, gid+8), cols (2tig, 2tig+1) per 16x8 tile
#pragma unroll
    for (int mt = 0; mt < 2; mt++) {
        int r0 = bm + wm + mt * 16 + gid;
        int r1 = r0 + 8;
#pragma unroll
        for (int nt = 0; nt < 8; nt++) {
            int col = bn + wn + nt * 8 + 2 * tig;
            if (r0 < N_NODES)
                *(float2*)(C + (size_t)r0 * D + col) =
                    make_float2(acc[mt][nt][0], acc[mt][nt][1]);
            if (r1 < N_NODES)
                *(float2*)(C + (size_t)r1 * D + col) =
                    make_float2(acc[mt][nt][2], acc[mt][nt][3]);
        }
    }
}

// ---------------- fused CSR aggregation + bias + LayerNorm + ReLU ----------------
template <bool SPLIT>
__global__ void agg_ln_kernel(const float* __restrict__ h,
                              const int* __restrict__ offsets,
                              const int* __restrict__ csr_src,
                              const float* __restrict__ csr_w,
                              const float* __restrict__ dinv,
                              const float* __restrict__ bias,
                              const float* __restrict__ lw,
                              const float* __restrict__ lb,
                              float* __restrict__ out_f,
                              __nv_bfloat16* __restrict__ out_h,
                              __nv_bfloat16* __restrict__ out_l) {
    int row = blockIdx.x * 8 + (threadIdx.x >> 5);
    int lane = threadIdx.x & 31;
    if (row >= N_NODES) return;

    float di = dinv[row];
    float sw = di * di;
    const float4* hp = (const float4*)(h + (size_t)row * D);
    float4 s0 = hp[lane], s1 = hp[lane + 32];
    float4 v0 = make_float4(s0.x * sw, s0.y * sw, s0.z * sw, s0.w * sw);
    float4 v1 = make_float4(s1.x * sw, s1.y * sw, s1.z * sw, s1.w * sw);

    int e0 = offsets[row];
    int e1 = offsets[row + 1];
    int e = e0;
    for (; e + 2 <= e1; e += 2) {
        int  sA = csr_src[e],   sB = csr_src[e + 1];
        float wA = csr_w[e],    wB = csr_w[e + 1];
        const float4* pA = (const float4*)(h + (size_t)sA * D);
        const float4* pB = (const float4*)(h + (size_t)sB * D);
        float4 a0 = pA[lane], a1 = pA[lane + 32];
        float4 b0 = pB[lane], b1 = pB[lane + 32];
        v0.x += a0.x * wA; v0.y += a0.y * wA; v0.z += a0.z * wA; v0.w += a0.w * wA;
        v1.x += a1.x * wA; v1.y += a1.y * wA; v1.z += a1.z * wA; v1.w += a1.w * wA;
        v0.x += b0.x * wB; v0.y += b0.y * wB; v0.z += b0.z * wB; v0.w += b0.w * wB;
        v1.x += b1.x * wB; v1.y += b1.y * wB; v1.z += b1.z * wB; v1.w += b1.w * wB;
    }
    if (e < e1) {
        int  sA = csr_src[e];
        float wA = csr_w[e];
        const float4* pA = (const float4*)(h + (size_t)sA * D);
        float4 a0 = pA[lane], a1 = pA[lane + 32];
        v0.x += a0.x * wA; v0.y += a0.y * wA; v0.z += a0.z * wA; v0.w += a0.w * wA;
        v1.x += a1.x * wA; v1.y += a1.y * wA; v1.z += a1.z * wA; v1.w += a1.w * wA;
    }

    const float4* bp = (const float4*)bias;
    float4 b0 = bp[lane], b1 = bp[lane + 32];
    v0.x += b0.x; v0.y += b0.y; v0.z += b0.z; v0.w += b0.w;
    v1.x += b1.x; v1.y += b1.y; v1.z += b1.z; v1.w += b1.w;

    float s = v0.x + v0.y + v0.z + v0.w + v1.x + v1.y + v1.z + v1.w;
#pragma unroll
    for (int o = 16; o > 0; o >>= 1) s += __shfl_xor_sync(0xffffffffu, s, o);
    float mu = s * (1.0f / D);

    v0.x -= mu; v0.y -= mu; v0.z -= mu; v0.w -= mu;
    v1.x -= mu; v1.y -= mu; v1.z -= mu; v1.w -= mu;
    float q = v0.x*v0.x + v0.y*v0.y + v0.z*v0.z + v0.w*v0.w
            + v1.x*v1.x + v1.y*v1.y + v1.z*v1.z + v1.w*v1.w;
#pragma unroll
    for (int o = 16; o > 0; o >>= 1) q += __shfl_xor_sync(0xffffffffu, q, o);
    float inv = rsqrtf(q * (1.0f / D) + LN_EPS);

    const float4* wp = (const float4*)lw;
    const float4* lp = (const float4*)lb;
    float4 w0 = wp[lane], w1 = wp[lane + 32];
    float4 l0 = lp[lane], l1 = lp[lane + 32];

    float4 o0, o1;
    o0.x = fmaxf(v0.x * inv * w0.x + l0.x, 0.f);
    o0.y = fmaxf(v0.y * inv * w0.y + l0.y, 0.f);
    o0.z = fmaxf(v0.z * inv * w0.z + l0.z, 0.f);
    o0.w = fmaxf(v0.w * inv * w0.w + l0.w, 0.f);
    o1.x = fmaxf(v1.x * inv * w1.x + l1.x, 0.f);
    o1.y = fmaxf(v1.y * inv * w1.y + l1.y, 0.f);
    o1.z = fmaxf(v1.z * inv * w1.z + l1.z, 0.f);
    o1.w = fmaxf(v1.w * inv * w1.w + l1.w, 0.f);

    if (SPLIT) {
        __nv_bfloat16 hh[8], ll[8];
        split_bf(o0.x, hh[0], ll[0]); split_bf(o0.y, hh[1], ll[1]);
        split_bf(o0.z, hh[2], ll[2]); split_bf(o0.w, hh[3], ll[3]);
        split_bf(o1.x, hh[4], ll[4]); split_bf(o1.y, hh[5], ll[5]);
        split_bf(o1.z, hh[6], ll[6]); split_bf(o1.w, hh[7], ll[7]);
        __nv_bfloat162* oh = (__nv_bfloat162*)(out_h + (size_t)row * D);
        __nv_bfloat162* ol = (__nv_bfloat162*)(out_l + (size_t)row * D);
        oh[2 * lane]          = __nv_bfloat162(hh[0], hh[1]);
        oh[2 * lane + 1]      = __nv_bfloat162(hh[2], hh[3]);
        oh[2 * lane + 64]     = __nv_bfloat162(hh[4], hh[5]);
        oh[2 * lane + 65]     = __nv_bfloat162(hh[6], hh[7]);
        ol[2 * lane]          = __nv_bfloat162(ll[0], ll[1]);
        ol[2 * lane + 1]      = __nv_bfloat162(ll[2], ll[3]);
        ol[2 * lane + 64]     = __nv_bfloat162(ll[4], ll[5]);
        ol[2 * lane + 65]     = __nv_bfloat162(ll[6], ll[7]);
    } else {
        float4* op = (float4*)(out_f + (size_t)row * D);
        op[lane] = o0;
        op[lane + 32] = o1;
    }
}

// ---------------- fused pool + head (batch is sorted) ----------------
__device__ __forceinline__ int lower_bound_dev(const int* a, int n, int key) {
    int lo = 0, hi = n;
    while (lo < hi) {
        int mid = (lo + hi) >> 1;
        if (a[mid] < key) lo = mid + 1; else hi = mid;
    }
    return lo;
}

__global__ void pool_head_kernel(const int* __restrict__ batch,
                                 const float* __restrict__ h,
                                 const float* __restrict__ linW,
                                 const float* __restrict__ linb,
                                 float* __restrict__ out) {
    __shared__ float row[D];
    __shared__ int s_start, s_end;
    int g = blockIdx.x;
    int c = threadIdx.x;
    if (c == 0) {
        s_start = lower_bound_dev(batch, N_NODES, g);
        s_end   = lower_bound_dev(batch, N_NODES, g + 1);
    }
    __syncthreads();
    int start = s_start, end = s_end;
    float sum = 0.0f;
    for (int n = start; n < end; n++) sum += h[(size_t)n * D + c];
    float cnt = (float)(end - start);
    row[c] = sum / fmaxf(cnt, 1.0f);
    __syncthreads();
    if (c < NC) {
        float acc = linb[c];
#pragma unroll 8
        for (int k = 0; k < D; k++) acc += row[k] * linW[k * NC + c];
        out[g * NC + c] = acc;
    }
}

// ---------------- launch ----------------
extern "C" void kernel_launch(void* const* d_in, const int* in_sizes, int n_in,
                              void* d_out, int out_size) {
    const float* x     = (const float*)d_in[0];
    const int*   ei    = (const int*)d_in[1];
    const int*   batch = (const int*)d_in[2];
    const float* W1    = (const float*)d_in[3];
    const float* b1    = (const float*)d_in[4];
    const float* W2    = (const float*)d_in[5];
    const float* b2    = (const float*)d_in[6];
    const float* ln1w  = (const float*)d_in[7];
    const float* ln1b  = (const float*)d_in[8];
    const float* ln2w  = (const float*)d_in[9];
    const float* ln2b  = (const float*)d_in[10];
    const float* linW  = (const float*)d_in[11];
    const float* linb  = (const float*)d_in[12];
    float* out = (float*)d_out;

    const int* src = ei;
    const int* dst = ei + N_EDGES;

    float *A, *B, *dinv, *csr_w;
    __nv_bfloat16 *XH, *XL, *w1h, *w1l, *w2h, *w2l;
    int *counts, *offsets, *cursor, *csr_src, *bsums;
    cudaGetSymbolAddress((void**)&A,       g_A);
    cudaGetSymbolAddress((void**)&B,       g_B);
    cudaGetSymbolAddress((void**)&XH,      g_xh);
    cudaGetSymbolAddress((void**)&XL,      g_xl);
    cudaGetSymbolAddress((void**)&w1h,     g_w1h);
    cudaGetSymbolAddress((void**)&w1l,     g_w1l);
    cudaGetSymbolAddress((void**)&w2h,     g_w2h);
    cudaGetSymbolAddress((void**)&w2l,     g_w2l);
    cudaGetSymbolAddress((void**)&dinv,    g_dinv);
    cudaGetSymbolAddress((void**)&counts,  g_counts);
    cudaGetSymbolAddress((void**)&offsets, g_offsets);
    cudaGetSymbolAddress((void**)&cursor,  g_cursor);
    cudaGetSymbolAddress((void**)&bsums,   g_bsums);
    cudaGetSymbolAddress((void**)&csr_src, g_csr_src);
    cudaGetSymbolAddress((void**)&csr_w,   g_csr_w);

    cudaFuncSetAttribute(gemm_bf16_kernel,
                         cudaFuncAttributeMaxDynamicSharedMemorySize, GEMM_SMEM);

    // prep: operand splits
    prep_x_kernel<<<(N_NODES * (D / 4) + 255) / 256, 256>>>(x, XH, XL);
    prep_w_kernel<<<D, D>>>(W1, w1h, w1l);
    prep_w_kernel<<<D, D>>>(W2, w2h, w2l);

    // CSR build
    count_zero_kernel<<<(N_NODES + 255) / 256, 256>>>(counts);
    deg_count_kernel<<<(N_EDGES + 255) / 256, 256>>>(dst, counts);
    scan_blocksum_kernel<<<SCAN_NB, SCAN_BLK>>>(counts, bsums);
    scan_sums_kernel<<<1, 128>>>(bsums);
    scan_local_kernel<<<SCAN_NB, SCAN_BLK>>>(counts, bsums, offsets, cursor, dinv);
    fill_kernel<<<(N_EDGES + 255) / 256, 256>>>(src, dst, dinv, cursor, csr_src, csr_w);

    dim3 ggrid(2, (N_NODES + 127) / 128);

    // layer 1
    gemm_bf16_kernel<<<ggrid, 256, GEMM_SMEM>>>(XH, XL, w1h, w1l, A);
    agg_ln_kernel<true><<<(N_NODES + 7) / 8, 256>>>(A, offsets, csr_src, csr_w, dinv,
                                                    b1, ln1w, ln1b, nullptr, XH, XL);
    // layer 2
    gemm_bf16_kernel<<<ggrid, 256, GEMM_SMEM>>>(XH, XL, w2h, w2l, A);
    agg_ln_kernel<false><<<(N_NODES + 7) / 8, 256>>>(A, offsets, csr_src, csr_w, dinv,
                                                     b2, ln2w, ln2b, B, nullptr, nullptr);

    // pool + head
    pool_head_kernel<<<NG, D>>>(batch, B, linW, linb, out);
}

// round 13
// speedup vs baseline: 1.9412x; 1.0786x over previous
#include <cuda_runtime.h>
#include <cuda_bf16.h>
#include <math.h>
#include <stdint.h>

#define N_NODES 50000
#define N_EDGES 800000
#define D 256
#define NG 512
#define NC 10
#define LN_EPS 1e-5f

#define SCAN_BLK 512
#define SCAN_NB ((N_NODES + SCAN_BLK - 1) / SCAN_BLK)   // 98

// ---------------- scratch (device globals; no allocation allowed) -------------
__device__ __align__(16) __nv_bfloat16 g_Abf[N_NODES * D];   // GEMM output (bf16)
__device__ __align__(16) float g_B[N_NODES * D];             // final activations
__device__ __align__(16) __nv_bfloat16 g_xh[N_NODES * D];    // bf16-hi operand
__device__ __align__(16) __nv_bfloat16 g_xl[N_NODES * D];    // bf16-lo operand
__device__ __align__(16) __nv_bfloat16 g_w1h[D * D], g_w1l[D * D];  // W1^T split
__device__ __align__(16) __nv_bfloat16 g_w2h[D * D], g_w2l[D * D];  // W2^T split
__device__ float g_dinv[N_NODES];
__device__ int   g_counts[N_NODES];
__device__ int   g_offsets[N_NODES + 1];
__device__ int   g_cursor[N_NODES];
__device__ int   g_bsums[SCAN_NB];
__device__ int   g_csr_src[N_EDGES];
__device__ float g_csr_w[N_EDGES];

// ---------------- helpers ----------------
__device__ __forceinline__ uint32_t sw128(uint32_t off) {
    return off ^ ((off >> 3) & 0x70);
}

__device__ __forceinline__ void split_bf(float v, __nv_bfloat16& h, __nv_bfloat16& l) {
    h = __float2bfloat16(v);
    l = __float2bfloat16(v - __bfloat162float(h));
}

// unpack 8 bf16 (uint4) to 8 floats
__device__ __forceinline__ void bf8_to_f(uint4 u, float* f) {
    const __nv_bfloat162* p = (const __nv_bfloat162*)&u;
#pragma unroll
    for (int i = 0; i < 4; i++) {
        float2 t = __bfloat1622float2(p[i]);
        f[2 * i]     = t.x;
        f[2 * i + 1] = t.y;
    }
}

#define MMA_BF16(d, a, b0, b1)                                              \
    asm volatile(                                                           \
        "mma.sync.aligned.m16n8k16.row.col.f32.bf16.bf16.f32 "              \
        "{%0,%1,%2,%3}, {%4,%5,%6,%7}, {%8,%9}, {%0,%1,%2,%3};"             \
        : "+f"((d)[0]), "+f"((d)[1]), "+f"((d)[2]), "+f"((d)[3])            \
        : "r"((a)[0]), "r"((a)[1]), "r"((a)[2]), "r"((a)[3]),               \
          "r"(b0), "r"(b1))

// ---------------- prep kernels ----------------
__global__ void prep_x_kernel(const float* __restrict__ x,
                              __nv_bfloat16* __restrict__ xh,
                              __nv_bfloat16* __restrict__ xl) {
    int i = blockIdx.x * blockDim.x + threadIdx.x;
    if (i < N_NODES * (D / 4)) {
        float4 v = ((const float4*)x)[i];
        __nv_bfloat16 h0, h1, h2, h3, l0, l1, l2, l3;
        split_bf(v.x, h0, l0);
        split_bf(v.y, h1, l1);
        split_bf(v.z, h2, l2);
        split_bf(v.w, h3, l3);
        __nv_bfloat162* xh2 = (__nv_bfloat162*)xh;
        __nv_bfloat162* xl2 = (__nv_bfloat162*)xl;
        xh2[2 * i]     = __nv_bfloat162(h0, h1);
        xh2[2 * i + 1] = __nv_bfloat162(h2, h3);
        xl2[2 * i]     = __nv_bfloat162(l0, l1);
        xl2[2 * i + 1] = __nv_bfloat162(l2, l3);
    }
}

// transpose + split: Wt[n][k] = W[k][n]
__global__ void prep_w_kernel(const float* __restrict__ W,
                              __nv_bfloat16* __restrict__ Wth,
                              __nv_bfloat16* __restrict__ Wtl) {
    int n = blockIdx.x;
    int k = threadIdx.x;
    float v = W[k * D + n];
    __nv_bfloat16 h, l;
    split_bf(v, h, l);
    Wth[n * D + k] = h;
    Wtl[n * D + k] = l;
}

// ---------------- degree / CSR ----------------
__global__ void count_zero_kernel(int* counts) {
    int i = blockIdx.x * blockDim.x + threadIdx.x;
    if (i < N_NODES) counts[i] = 0;
}

__global__ void deg_count_kernel(const int* __restrict__ dst, int* counts) {
    int e = blockIdx.x * blockDim.x + threadIdx.x;
    if (e < N_EDGES) atomicAdd(&counts[dst[e]], 1);
}

__global__ void scan_blocksum_kernel(const int* __restrict__ counts, int* __restrict__ bsums) {
    int t = threadIdx.x;
    int i = blockIdx.x * SCAN_BLK + t;
    int v = (i < N_NODES) ? counts[i] : 0;
#pragma unroll
    for (int o = 16; o > 0; o >>= 1) v += __shfl_xor_sync(0xffffffffu, v, o);
    __shared__ int ws[SCAN_BLK / 32];
    if ((t & 31) == 0) ws[t >> 5] = v;
    __syncthreads();
    if (t == 0) {
        int s = 0;
#pragma unroll
        for (int w = 0; w < SCAN_BLK / 32; w++) s += ws[w];
        bsums[blockIdx.x] = s;
    }
}

__global__ void scan_sums_kernel(int* bsums) {
    int t = threadIdx.x;
    int lane = t & 31, w = t >> 5;
    int v = (t < SCAN_NB) ? bsums[t] : 0;
    int inc = v;
#pragma unroll
    for (int o = 1; o < 32; o <<= 1) {
        int n = __shfl_up_sync(0xffffffffu, inc, o);
        if (lane >= o) inc += n;
    }
    __shared__ int ws[4];
    if (lane == 31) ws[w] = inc;
    __syncthreads();
    int add = 0;
    for (int k = 0; k < w; k++) add += ws[k];
    if (t < SCAN_NB) bsums[t] = inc - v + add;
}

__global__ void scan_local_kernel(const int* __restrict__ counts,
                                  const int* __restrict__ bsums,
                                  int* __restrict__ offsets,
                                  int* __restrict__ cursor,
                                  float* __restrict__ dinv) {
    int t = threadIdx.x;
    int lane = t & 31, w = t >> 5;
    int i = blockIdx.x * SCAN_BLK + t;
    int v = (i < N_NODES) ? counts[i] : 0;
    int inc = v;
#pragma unroll
    for (int o = 1; o < 32; o <<= 1) {
        int n = __shfl_up_sync(0xffffffffu, inc, o);
        if (lane >= o) inc += n;
    }
    __shared__ int ws[SCAN_BLK / 32];
    if (lane == 31) ws[w] = inc;
    __syncthreads();
    int add = bsums[blockIdx.x];
    for (int k = 0; k < w; k++) add += ws[k];
    int excl = inc - v + add;
    if (i < N_NODES) {
        offsets[i] = excl;
        cursor[i] = excl;
        dinv[i] = rsqrtf((float)(v + 1));
        if (i == N_NODES - 1) offsets[N_NODES] = excl + v;
    }
}

__global__ void fill_kernel(const int* __restrict__ src, const int* __restrict__ dst,
                            const float* __restrict__ dinv,
                            int* cursor, int* __restrict__ csr_src, float* __restrict__ csr_w) {
    int e = blockIdx.x * blockDim.x + threadIdx.x;
    if (e < N_EDGES) {
        int s = src[e], d = dst[e];
        int pos = atomicAdd(&cursor[d], 1);
        csr_src[pos] = s;
        csr_w[pos] = dinv[s] * dinv[d];
    }
}

// ------- bf16 mma.sync 3-pass GEMM: Cbf[M,256] = A @ W  (Wt[n][k] operands) ----
// CTA tile 128x128, 8 warps (warp tile 32x64), K chunks of 64, sw128 smem.
#define KC 64
#define NKCH (D / KC)            // 4
#define TILEB (128 * 128)        // bytes per operand tile (128 rows x 64 bf16)
#define GEMM_SMEM (4 * TILEB)    // 65536

__global__ __launch_bounds__(256, 2)
void gemm_bf16_kernel(const __nv_bfloat16* __restrict__ Ah,
                      const __nv_bfloat16* __restrict__ Al,
                      const __nv_bfloat16* __restrict__ Bh,
                      const __nv_bfloat16* __restrict__ Bl,
                      __nv_bfloat16* __restrict__ C) {
    extern __shared__ char smc[];
    char* sAh = smc;
    char* sAl = smc + TILEB;
    char* sBh = smc + 2 * TILEB;
    char* sBl = smc + 3 * TILEB;

    int tid = threadIdx.x;
    int lane = tid & 31;
    int w = tid >> 5;
    int bm = blockIdx.y * 128;
    int bn = blockIdx.x * 128;
    int wm = (w & 3) * 32;
    int wn = (w >> 2) * 64;
    int gid = lane >> 2;         // 0..7
    int tig = lane & 3;          // 0..3

    float acc[2][8][4];
#pragma unroll
    for (int mt = 0; mt < 2; mt++)
#pragma unroll
        for (int nt = 0; nt < 8; nt++)
#pragma unroll
            for (int i = 0; i < 4; i++) acc[mt][nt][i] = 0.0f;

    for (int c = 0; c < NKCH; c++) {
        // global -> smem: each thread moves 4 float4 per tile (8 bf16 each)
#pragma unroll
        for (int t = 0; t < 4; t++) {
            int idx = tid + t * 256;       // 0..1023
            int row = idx >> 3;            // 0..127
            int f4  = idx & 7;             // 0..7 (16B slots in 128B row)
            uint32_t so = sw128((uint32_t)(row * 128 + f4 * 16));
            int ar = bm + row;
            float4 vh = make_float4(0.f, 0.f, 0.f, 0.f);
            float4 vl = make_float4(0.f, 0.f, 0.f, 0.f);
            if (ar < N_NODES) {
                size_t gi = (size_t)ar * 32 + c * 8 + f4;   // float4 units of 256-bf16 row
                vh = ((const float4*)Ah)[gi];
                vl = ((const float4*)Al)[gi];
            }
            *(float4*)(sAh + so) = vh;
            *(float4*)(sAl + so) = vl;
            size_t wi = (size_t)(bn + row) * 32 + c * 8 + f4;
            *(float4*)(sBh + so) = ((const float4*)Bh)[wi];
            *(float4*)(sBl + so) = ((const float4*)Bl)[wi];
        }
        __syncthreads();

#pragma unroll
        for (int ks = 0; ks < 4; ks++) {
            int kb = ks * 32 + tig * 4;    // byte offset of this thread's k-pair
            uint32_t ah[2][4], al[2][4];
#pragma unroll
            for (int mt = 0; mt < 2; mt++) {
                int m0 = wm + mt * 16 + gid;
                ah[mt][0] = *(const uint32_t*)(sAh + sw128((uint32_t)(m0 * 128 + kb)));
                ah[mt][1] = *(const uint32_t*)(sAh + sw128((uint32_t)((m0 + 8) * 128 + kb)));
                ah[mt][2] = *(const uint32_t*)(sAh + sw128((uint32_t)(m0 * 128 + kb + 16)));
                ah[mt][3] = *(const uint32_t*)(sAh + sw128((uint32_t)((m0 + 8) * 128 + kb + 16)));
                al[mt][0] = *(const uint32_t*)(sAl + sw128((uint32_t)(m0 * 128 + kb)));
                al[mt][1] = *(const uint32_t*)(sAl + sw128((uint32_t)((m0 + 8) * 128 + kb)));
                al[mt][2] = *(const uint32_t*)(sAl + sw128((uint32_t)(m0 * 128 + kb + 16)));
                al[mt][3] = *(const uint32_t*)(sAl + sw128((uint32_t)((m0 + 8) * 128 + kb + 16)));
            }
#pragma unroll
            for (int nt = 0; nt < 8; nt++) {
                int n0 = wn + nt * 8 + gid;
                uint32_t bh0 = *(const uint32_t*)(sBh + sw128((uint32_t)(n0 * 128 + kb)));
                uint32_t bh1 = *(const uint32_t*)(sBh + sw128((uint32_t)(n0 * 128 + kb + 16)));
                uint32_t bl0 = *(const uint32_t*)(sBl + sw128((uint32_t)(n0 * 128 + kb)));
                uint32_t bl1 = *(const uint32_t*)(sBl + sw128((uint32_t)(n0 * 128 + kb + 16)));
#pragma unroll
                for (int mt = 0; mt < 2; mt++) {
                    MMA_BF16(acc[mt][nt], ah[mt], bh0, bh1);
                    MMA_BF16(acc[mt][nt], al[mt], bh0, bh1);
                    MMA_BF16(acc[mt][nt], ah[mt], bl0, bl1);
                }
            }
        }
        __syncthreads();
    }

    // epilogue (bf16): thread owns rows (gid, gid+8), cols (2tig, 2tig+1) per tile
#pragma unroll
    for (int mt = 0; mt < 2; mt++) {
        int r0 = bm + wm + mt * 16 + gid;
        int r1 = r0 + 8;
#pragma unroll
        for (int nt = 0; nt < 8; nt++) {
            int col = bn + wn + nt * 8 + 2 * tig;
            if (r0 < N_NODES)
                *(__nv_bfloat162*)(C + (size_t)r0 * D + col) =
                    __floats2bfloat162_rn(acc[mt][nt][0], acc[mt][nt][1]);
            if (r1 < N_NODES)
                *(__nv_bfloat162*)(C + (size_t)r1 * D + col) =
                    __floats2bfloat162_rn(acc[mt][nt][2], acc[mt][nt][3]);
        }
    }
}

// -------- fused CSR aggregation (bf16 gather) + bias + LayerNorm + ReLU -------
// one warp per node; each lane owns 8 consecutive columns (one uint4 = 8 bf16)
template <bool SPLIT>
__global__ void agg_ln_kernel(const __nv_bfloat16* __restrict__ h,
                              const int* __restrict__ offsets,
                              const int* __restrict__ csr_src,
                              const float* __restrict__ csr_w,
                              const float* __restrict__ dinv,
                              const float* __restrict__ bias,
                              const float* __restrict__ lw,
                              const float* __restrict__ lb,
                              float* __restrict__ out_f,
                              __nv_bfloat16* __restrict__ out_h,
                              __nv_bfloat16* __restrict__ out_l) {
    int row = blockIdx.x * 8 + (threadIdx.x >> 5);
    int lane = threadIdx.x & 31;
    if (row >= N_NODES) return;

    float di = dinv[row];
    float sw = di * di;

    float acc[8], f[8];
    {
        uint4 u = *(const uint4*)(h + (size_t)row * D + lane * 8);
        bf8_to_f(u, f);
#pragma unroll
        for (int j = 0; j < 8; j++) acc[j] = f[j] * sw;
    }

    int e0 = offsets[row];
    int e1 = offsets[row + 1];
    int e = e0;
    for (; e + 2 <= e1; e += 2) {
        int  sA = csr_src[e],   sB = csr_src[e + 1];
        float wA = csr_w[e],    wB = csr_w[e + 1];
        uint4 uA = *(const uint4*)(h + (size_t)sA * D + lane * 8);
        uint4 uB = *(const uint4*)(h + (size_t)sB * D + lane * 8);
        float fa[8], fb[8];
        bf8_to_f(uA, fa);
        bf8_to_f(uB, fb);
#pragma unroll
        for (int j = 0; j < 8; j++) acc[j] += fa[j] * wA + fb[j] * wB;
    }
    if (e < e1) {
        int  sA = csr_src[e];
        float wA = csr_w[e];
        uint4 uA = *(const uint4*)(h + (size_t)sA * D + lane * 8);
        bf8_to_f(uA, f);
#pragma unroll
        for (int j = 0; j < 8; j++) acc[j] += f[j] * wA;
    }

    // + bias
    {
        float4 b0 = ((const float4*)bias)[2 * lane];
        float4 b1 = ((const float4*)bias)[2 * lane + 1];
        acc[0] += b0.x; acc[1] += b0.y; acc[2] += b0.z; acc[3] += b0.w;
        acc[4] += b1.x; acc[5] += b1.y; acc[6] += b1.z; acc[7] += b1.w;
    }

    // LayerNorm
    float s = 0.f;
#pragma unroll
    for (int j = 0; j < 8; j++) s += acc[j];
#pragma unroll
    for (int o = 16; o > 0; o >>= 1) s += __shfl_xor_sync(0xffffffffu, s, o);
    float mu = s * (1.0f / D);

    float q = 0.f;
#pragma unroll
    for (int j = 0; j < 8; j++) {
        acc[j] -= mu;
        q += acc[j] * acc[j];
    }
#pragma unroll
    for (int o = 16; o > 0; o >>= 1) q += __shfl_xor_sync(0xffffffffu, q, o);
    float inv = rsqrtf(q * (1.0f / D) + LN_EPS);

    float4 w0 = ((const float4*)lw)[2 * lane];
    float4 w1 = ((const float4*)lw)[2 * lane + 1];
    float4 l0 = ((const float4*)lb)[2 * lane];
    float4 l1 = ((const float4*)lb)[2 * lane + 1];
    float wv[8] = {w0.x, w0.y, w0.z, w0.w, w1.x, w1.y, w1.z, w1.w};
    float lv[8] = {l0.x, l0.y, l0.z, l0.w, l1.x, l1.y, l1.z, l1.w};

    float o8[8];
#pragma unroll
    for (int j = 0; j < 8; j++)
        o8[j] = fmaxf(acc[j] * inv * wv[j] + lv[j], 0.f);

    if (SPLIT) {
        __nv_bfloat16 hh[8], ll[8];
#pragma unroll
        for (int j = 0; j < 8; j++) split_bf(o8[j], hh[j], ll[j]);
        uint4 uh, ul;
        __nv_bfloat162* ph = (__nv_bfloat162*)&uh;
        __nv_bfloat162* pl = (__nv_bfloat162*)&ul;
#pragma unroll
        for (int i = 0; i < 4; i++) {
            ph[i] = __nv_bfloat162(hh[2 * i], hh[2 * i + 1]);
            pl[i] = __nv_bfloat162(ll[2 * i], ll[2 * i + 1]);
        }
        *(uint4*)(out_h + (size_t)row * D + lane * 8) = uh;
        *(uint4*)(out_l + (size_t)row * D + lane * 8) = ul;
    } else {
        float4* op = (float4*)(out_f + (size_t)row * D + lane * 8);
        op[0] = make_float4(o8[0], o8[1], o8[2], o8[3]);
        op[1] = make_float4(o8[4], o8[5], o8[6], o8[7]);
    }
}

// ---------------- fused pool + head (batch is sorted) ----------------
__device__ __forceinline__ int lower_bound_dev(const int* a, int n, int key) {
    int lo = 0, hi = n;
    while (lo < hi) {
        int mid = (lo + hi) >> 1;
        if (a[mid] < key) lo = mid + 1; else hi = mid;
    }
    return lo;
}

__global__ void pool_head_kernel(const int* __restrict__ batch,
                                 const float* __restrict__ h,
                                 const float* __restrict__ linW,
                                 const float* __restrict__ linb,
                                 float* __restrict__ out) {
    __shared__ float row[D];
    __shared__ int s_start, s_end;
    int g = blockIdx.x;
    int c = threadIdx.x;
    if (c == 0) {
        s_start = lower_bound_dev(batch, N_NODES, g);
        s_end   = lower_bound_dev(batch, N_NODES, g + 1);
    }
    __syncthreads();
    int start = s_start, end = s_end;
    float sum = 0.0f;
    for (int n = start; n < end; n++) sum += h[(size_t)n * D + c];
    float cnt = (float)(end - start);
    row[c] = sum / fmaxf(cnt, 1.0f);
    __syncthreads();
    if (c < NC) {
        float acc = linb[c];
#pragma unroll 8
        for (int k = 0; k < D; k++) acc += row[k] * linW[k * NC + c];
        out[g * NC + c] = acc;
    }
}

// ---------------- launch ----------------
extern "C" void kernel_launch(void* const* d_in, const int* in_sizes, int n_in,
                              void* d_out, int out_size) {
    const float* x     = (const float*)d_in[0];
    const int*   ei    = (const int*)d_in[1];
    const int*   batch = (const int*)d_in[2];
    const float* W1    = (const float*)d_in[3];
    const float* b1    = (const float*)d_in[4];
    const float* W2    = (const float*)d_in[5];
    const float* b2    = (const float*)d_in[6];
    const float* ln1w  = (const float*)d_in[7];
    const float* ln1b  = (const float*)d_in[8];
    const float* ln2w  = (const float*)d_in[9];
    const float* ln2b  = (const float*)d_in[10];
    const float* linW  = (const float*)d_in[11];
    const float* linb  = (const float*)d_in[12];
    float* out = (float*)d_out;

    const int* src = ei;
    const int* dst = ei + N_EDGES;

    float *B, *dinv, *csr_w;
    __nv_bfloat16 *Abf, *XH, *XL, *w1h, *w1l, *w2h, *w2l;
    int *counts, *offsets, *cursor, *csr_src, *bsums;
    cudaGetSymbolAddress((void**)&Abf,     g_Abf);
    cudaGetSymbolAddress((void**)&B,       g_B);
    cudaGetSymbolAddress((void**)&XH,      g_xh);
    cudaGetSymbolAddress((void**)&XL,      g_xl);
    cudaGetSymbolAddress((void**)&w1h,     g_w1h);
    cudaGetSymbolAddress((void**)&w1l,     g_w1l);
    cudaGetSymbolAddress((void**)&w2h,     g_w2h);
    cudaGetSymbolAddress((void**)&w2l,     g_w2l);
    cudaGetSymbolAddress((void**)&dinv,    g_dinv);
    cudaGetSymbolAddress((void**)&counts,  g_counts);
    cudaGetSymbolAddress((void**)&offsets, g_offsets);
    cudaGetSymbolAddress((void**)&cursor,  g_cursor);
    cudaGetSymbolAddress((void**)&bsums,   g_bsums);
    cudaGetSymbolAddress((void**)&csr_src, g_csr_src);
    cudaGetSymbolAddress((void**)&csr_w,   g_csr_w);

    cudaFuncSetAttribute(gemm_bf16_kernel,
                         cudaFuncAttributeMaxDynamicSharedMemorySize, GEMM_SMEM);

    // prep: operand splits
    prep_x_kernel<<<(N_NODES * (D / 4) + 255) / 256, 256>>>(x, XH, XL);
    prep_w_kernel<<<D, D>>>(W1, w1h, w1l);
    prep_w_kernel<<<D, D>>>(W2, w2h, w2l);

    // CSR build
    count_zero_kernel<<<(N_NODES + 255) / 256, 256>>>(counts);
    deg_count_kernel<<<(N_EDGES + 255) / 256, 256>>>(dst, counts);
    scan_blocksum_kernel<<<SCAN_NB, SCAN_BLK>>>(counts, bsums);
    scan_sums_kernel<<<1, 128>>>(bsums);
    scan_local_kernel<<<SCAN_NB, SCAN_BLK>>>(counts, bsums, offsets, cursor, dinv);
    fill_kernel<<<(N_EDGES + 255) / 256, 256>>>(src, dst, dinv, cursor, csr_src, csr_w);

    dim3 ggrid(2, (N_NODES + 127) / 128);

    // layer 1
    gemm_bf16_kernel<<<ggrid, 256, GEMM_SMEM>>>(XH, XL, w1h, w1l, Abf);
    agg_ln_kernel<true><<<(N_NODES + 7) / 8, 256>>>(Abf, offsets, csr_src, csr_w, dinv,
                                                    b1, ln1w, ln1b, nullptr, XH, XL);
    // layer 2
    gemm_bf16_kernel<<<ggrid, 256, GEMM_SMEM>>>(XH, XL, w2h, w2l, Abf);
    agg_ln_kernel<false><<<(N_NODES + 7) / 8, 256>>>(Abf, offsets, csr_src, csr_w, dinv,
                                                     b2, ln2w, ln2b, B, nullptr, nullptr);

    // pool + head
    pool_head_kernel<<<NG, D>>>(batch, B, linW, linb, out);
}

// round 14
// speedup vs baseline: 2.0000x; 1.0303x over previous
#include <cuda_runtime.h>
#include <cuda_bf16.h>
#include <math.h>
#include <stdint.h>

#define N_NODES 50000
#define N_EDGES 800000
#define D 256
#define NG 512
#define NC 10
#define LN_EPS 1e-5f

#define SCAN_BLK 512
#define SCAN_NB ((N_NODES + SCAN_BLK - 1) / SCAN_BLK)   // 98

// ---------------- scratch (device globals; no allocation allowed) -------------
__device__ __align__(16) __nv_bfloat16 g_Abf[N_NODES * D];   // GEMM output (bf16)
__device__ __align__(16) __nv_bfloat16 g_Bbf[N_NODES * D];   // final activations (bf16)
__device__ __align__(16) __nv_bfloat16 g_xh[N_NODES * D];    // bf16-hi operand
__device__ __align__(16) __nv_bfloat16 g_xl[N_NODES * D];    // bf16-lo operand
__device__ __align__(16) __nv_bfloat16 g_w1h[D * D], g_w1l[D * D];  // W1^T split
__device__ __align__(16) __nv_bfloat16 g_w2h[D * D], g_w2l[D * D];  // W2^T split
__device__ float g_dinv[N_NODES];
__device__ int   g_counts[N_NODES];
__device__ int   g_offsets[N_NODES + 1];
__device__ int   g_cursor[N_NODES];
__device__ int   g_bsums[SCAN_NB];
__device__ int   g_csr_src[N_EDGES];

// ---------------- helpers ----------------
__device__ __forceinline__ uint32_t sw128(uint32_t off) {
    return off ^ ((off >> 3) & 0x70);
}

__device__ __forceinline__ void split_bf(float v, __nv_bfloat16& h, __nv_bfloat16& l) {
    h = __float2bfloat16(v);
    l = __float2bfloat16(v - __bfloat162float(h));
}

// unpack 8 bf16 (uint4) to 8 floats
__device__ __forceinline__ void bf8_to_f(uint4 u, float* f) {
    const __nv_bfloat162* p = (const __nv_bfloat162*)&u;
#pragma unroll
    for (int i = 0; i < 4; i++) {
        float2 t = __bfloat1622float2(p[i]);
        f[2 * i]     = t.x;
        f[2 * i + 1] = t.y;
    }
}

#define MMA_BF16(d, a, b0, b1)                                              \
    asm volatile(                                                           \
        "mma.sync.aligned.m16n8k16.row.col.f32.bf16.bf16.f32 "              \
        "{%0,%1,%2,%3}, {%4,%5,%6,%7}, {%8,%9}, {%0,%1,%2,%3};"             \
        : "+f"((d)[0]), "+f"((d)[1]), "+f"((d)[2]), "+f"((d)[3])            \
        : "r"((a)[0]), "r"((a)[1]), "r"((a)[2]), "r"((a)[3]),               \
          "r"(b0), "r"(b1))

// ---------------- prep kernels ----------------
// also zeroes counts (fused former count_zero_kernel)
__global__ void prep_x_kernel(const float* __restrict__ x,
                              __nv_bfloat16* __restrict__ xh,
                              __nv_bfloat16* __restrict__ xl,
                              int* __restrict__ counts) {
    int i = blockIdx.x * blockDim.x + threadIdx.x;
    if (i < N_NODES) counts[i] = 0;
    if (i < N_NODES * (D / 4)) {
        float4 v = ((const float4*)x)[i];
        __nv_bfloat16 h0, h1, h2, h3, l0, l1, l2, l3;
        split_bf(v.x, h0, l0);
        split_bf(v.y, h1, l1);
        split_bf(v.z, h2, l2);
        split_bf(v.w, h3, l3);
        __nv_bfloat162* xh2 = (__nv_bfloat162*)xh;
        __nv_bfloat162* xl2 = (__nv_bfloat162*)xl;
        xh2[2 * i]     = __nv_bfloat162(h0, h1);
        xh2[2 * i + 1] = __nv_bfloat162(h2, h3);
        xl2[2 * i]     = __nv_bfloat162(l0, l1);
        xl2[2 * i + 1] = __nv_bfloat162(l2, l3);
    }
}

// transpose + split both weights in one launch: blocks [0,D) -> W1, [D,2D) -> W2
__global__ void prep_w_kernel(const float* __restrict__ W1,
                              const float* __restrict__ W2,
                              __nv_bfloat16* __restrict__ W1th,
                              __nv_bfloat16* __restrict__ W1tl,
                              __nv_bfloat16* __restrict__ W2th,
                              __nv_bfloat16* __restrict__ W2tl) {
    int b = blockIdx.x;
    int n = b & (D - 1);
    int k = threadIdx.x;
    const float* W = (b < D) ? W1 : W2;
    __nv_bfloat16* Th = (b < D) ? W1th : W2th;
    __nv_bfloat16* Tl = (b < D) ? W1tl : W2tl;
    float v = W[k * D + n];
    __nv_bfloat16 h, l;
    split_bf(v, h, l);
    Th[n * D + k] = h;
    Tl[n * D + k] = l;
}

// ---------------- degree / CSR ----------------
__global__ void deg_count_kernel(const int* __restrict__ dst, int* counts) {
    int e = blockIdx.x * blockDim.x + threadIdx.x;
    if (e < N_EDGES) atomicAdd(&counts[dst[e]], 1);
}

__global__ void scan_blocksum_kernel(const int* __restrict__ counts, int* __restrict__ bsums) {
    int t = threadIdx.x;
    int i = blockIdx.x * SCAN_BLK + t;
    int v = (i < N_NODES) ? counts[i] : 0;
#pragma unroll
    for (int o = 16; o > 0; o >>= 1) v += __shfl_xor_sync(0xffffffffu, v, o);
    __shared__ int ws[SCAN_BLK / 32];
    if ((t & 31) == 0) ws[t >> 5] = v;
    __syncthreads();
    if (t == 0) {
        int s = 0;
#pragma unroll
        for (int w = 0; w < SCAN_BLK / 32; w++) s += ws[w];
        bsums[blockIdx.x] = s;
    }
}

__global__ void scan_sums_kernel(int* bsums) {
    int t = threadIdx.x;
    int lane = t & 31, w = t >> 5;
    int v = (t < SCAN_NB) ? bsums[t] : 0;
    int inc = v;
#pragma unroll
    for (int o = 1; o < 32; o <<= 1) {
        int n = __shfl_up_sync(0xffffffffu, inc, o);
        if (lane >= o) inc += n;
    }
    __shared__ int ws[4];
    if (lane == 31) ws[w] = inc;
    __syncthreads();
    int add = 0;
    for (int k = 0; k < w; k++) add += ws[k];
    if (t < SCAN_NB) bsums[t] = inc - v + add;
}

__global__ void scan_local_kernel(const int* __restrict__ counts,
                                  const int* __restrict__ bsums,
                                  int* __restrict__ offsets,
                                  int* __restrict__ cursor,
                                  float* __restrict__ dinv) {
    int t = threadIdx.x;
    int lane = t & 31, w = t >> 5;
    int i = blockIdx.x * SCAN_BLK + t;
    int v = (i < N_NODES) ? counts[i] : 0;
    int inc = v;
#pragma unroll
    for (int o = 1; o < 32; o <<= 1) {
        int n = __shfl_up_sync(0xffffffffu, inc, o);
        if (lane >= o) inc += n;
    }
    __shared__ int ws[SCAN_BLK / 32];
    if (lane == 31) ws[w] = inc;
    __syncthreads();
    int add = bsums[blockIdx.x];
    for (int k = 0; k < w; k++) add += ws[k];
    int excl = inc - v + add;
    if (i < N_NODES) {
        offsets[i] = excl;
        cursor[i] = excl;
        dinv[i] = rsqrtf((float)(v + 1));
        if (i == N_NODES - 1) offsets[N_NODES] = excl + v;
    }
}

__global__ void fill_kernel(const int* __restrict__ src, const int* __restrict__ dst,
                            int* cursor, int* __restrict__ csr_src) {
    int e = blockIdx.x * blockDim.x + threadIdx.x;
    if (e < N_EDGES) {
        int s = src[e], d = dst[e];
        int pos = atomicAdd(&cursor[d], 1);
        csr_src[pos] = s;
    }
}

// ------- bf16 mma.sync 3-pass GEMM: Cbf[M,256] = A @ W  (Wt[n][k] operands) ----
// CTA tile 128x128, 8 warps (warp tile 32x64), K chunks of 64, sw128 smem.
#define KC 64
#define NKCH (D / KC)            // 4
#define TILEB (128 * 128)        // bytes per operand tile (128 rows x 64 bf16)
#define GEMM_SMEM (4 * TILEB)    // 65536

__global__ __launch_bounds__(256, 2)
void gemm_bf16_kernel(const __nv_bfloat16* __restrict__ Ah,
                      const __nv_bfloat16* __restrict__ Al,
                      const __nv_bfloat16* __restrict__ Bh,
                      const __nv_bfloat16* __restrict__ Bl,
                      __nv_bfloat16* __restrict__ C) {
    extern __shared__ char smc[];
    char* sAh = smc;
    char* sAl = smc + TILEB;
    char* sBh = smc + 2 * TILEB;
    char* sBl = smc + 3 * TILEB;

    int tid = threadIdx.x;
    int lane = tid & 31;
    int w = tid >> 5;
    int bm = blockIdx.y * 128;
    int bn = blockIdx.x * 128;
    int wm = (w & 3) * 32;
    int wn = (w >> 2) * 64;
    int gid = lane >> 2;         // 0..7
    int tig = lane & 3;          // 0..3

    float acc[2][8][4];
#pragma unroll
    for (int mt = 0; mt < 2; mt++)
#pragma unroll
        for (int nt = 0; nt < 8; nt++)
#pragma unroll
            for (int i = 0; i < 4; i++) acc[mt][nt][i] = 0.0f;

    for (int c = 0; c < NKCH; c++) {
        // global -> smem: each thread moves 4 float4 per tile (8 bf16 each)
#pragma unroll
        for (int t = 0; t < 4; t++) {
            int idx = tid + t * 256;       // 0..1023
            int row = idx >> 3;            // 0..127
            int f4  = idx & 7;             // 0..7 (16B slots in 128B row)
            uint32_t so = sw128((uint32_t)(row * 128 + f4 * 16));
            int ar = bm + row;
            float4 vh = make_float4(0.f, 0.f, 0.f, 0.f);
            float4 vl = make_float4(0.f, 0.f, 0.f, 0.f);
            if (ar < N_NODES) {
                size_t gi = (size_t)ar * 32 + c * 8 + f4;   // float4 units of 256-bf16 row
                vh = ((const float4*)Ah)[gi];
                vl = ((const float4*)Al)[gi];
            }
            *(float4*)(sAh + so) = vh;
            *(float4*)(sAl + so) = vl;
            size_t wi = (size_t)(bn + row) * 32 + c * 8 + f4;
            *(float4*)(sBh + so) = ((const float4*)Bh)[wi];
            *(float4*)(sBl + so) = ((const float4*)Bl)[wi];
        }
        __syncthreads();

#pragma unroll
        for (int ks = 0; ks < 4; ks++) {
            int kb = ks * 32 + tig * 4;    // byte offset of this thread's k-pair
            uint32_t ah[2][4], al[2][4];
#pragma unroll
            for (int mt = 0; mt < 2; mt++) {
                int m0 = wm + mt * 16 + gid;
                ah[mt][0] = *(const uint32_t*)(sAh + sw128((uint32_t)(m0 * 128 + kb)));
                ah[mt][1] = *(const uint32_t*)(sAh + sw128((uint32_t)((m0 + 8) * 128 + kb)));
                ah[mt][2] = *(const uint32_t*)(sAh + sw128((uint32_t)(m0 * 128 + kb + 16)));
                ah[mt][3] = *(const uint32_t*)(sAh + sw128((uint32_t)((m0 + 8) * 128 + kb + 16)));
                al[mt][0] = *(const uint32_t*)(sAl + sw128((uint32_t)(m0 * 128 + kb)));
                al[mt][1] = *(const uint32_t*)(sAl + sw128((uint32_t)((m0 + 8) * 128 + kb)));
                al[mt][2] = *(const uint32_t*)(sAl + sw128((uint32_t)(m0 * 128 + kb + 16)));
                al[mt][3] = *(const uint32_t*)(sAl + sw128((uint32_t)((m0 + 8) * 128 + kb + 16)));
            }
#pragma unroll
            for (int nt = 0; nt < 8; nt++) {
                int n0 = wn + nt * 8 + gid;
                uint32_t bh0 = *(const uint32_t*)(sBh + sw128((uint32_t)(n0 * 128 + kb)));
                uint32_t bh1 = *(const uint32_t*)(sBh + sw128((uint32_t)(n0 * 128 + kb + 16)));
                uint32_t bl0 = *(const uint32_t*)(sBl + sw128((uint32_t)(n0 * 128 + kb)));
                uint32_t bl1 = *(const uint32_t*)(sBl + sw128((uint32_t)(n0 * 128 + kb + 16)));
#pragma unroll
                for (int mt = 0; mt < 2; mt++) {
                    MMA_BF16(acc[mt][nt], ah[mt], bh0, bh1);
                    MMA_BF16(acc[mt][nt], al[mt], bh0, bh1);
                    MMA_BF16(acc[mt][nt], ah[mt], bl0, bl1);
                }
            }
        }
        __syncthreads();
    }

    // epilogue (bf16): thread owns rows (gid, gid+8), cols (2tig, 2tig+1) per tile
#pragma unroll
    for (int mt = 0; mt < 2; mt++) {
        int r0 = bm + wm + mt * 16 + gid;
        int r1 = r0 + 8;
#pragma unroll
        for (int nt = 0; nt < 8; nt++) {
            int col = bn + wn + nt * 8 + 2 * tig;
            if (r0 < N_NODES)
                *(__nv_bfloat162*)(C + (size_t)r0 * D + col) =
                    __floats2bfloat162_rn(acc[mt][nt][0], acc[mt][nt][1]);
            if (r1 < N_NODES)
                *(__nv_bfloat162*)(C + (size_t)r1 * D + col) =
                    __floats2bfloat162_rn(acc[mt][nt][2], acc[mt][nt][3]);
        }
    }
}

// -------- fused CSR aggregation (bf16 gather, MLP-4) + bias + LN + ReLU -------
// one warp per node; each lane owns 8 consecutive columns (one uint4 = 8 bf16)
template <bool SPLIT>
__global__ void agg_ln_kernel(const __nv_bfloat16* __restrict__ h,
                              const int* __restrict__ offsets,
                              const int* __restrict__ csr_src,
                              const float* __restrict__ dinv,
                              const float* __restrict__ bias,
                              const float* __restrict__ lw,
                              const float* __restrict__ lb,
                              __nv_bfloat16* __restrict__ out_h,
                              __nv_bfloat16* __restrict__ out_l) {
    int row = blockIdx.x * 8 + (threadIdx.x >> 5);
    int lane = threadIdx.x & 31;
    if (row >= N_NODES) return;

    float di = dinv[row];
    float sw = di * di;

    float acc[8], f[8];
    {
        uint4 u = *(const uint4*)(h + (size_t)row * D + lane * 8);
        bf8_to_f(u, f);
#pragma unroll
        for (int j = 0; j < 8; j++) acc[j] = f[j] * sw;
    }

    int e0 = offsets[row];
    int e1 = offsets[row + 1];
    int e = e0;
    // 4-way unrolled: 4 independent gathers in flight
    for (; e + 4 <= e1; e += 4) {
        int s0 = csr_src[e],     s1 = csr_src[e + 1];
        int s2 = csr_src[e + 2], s3 = csr_src[e + 3];
        float w0 = dinv[s0] * di, w1 = dinv[s1] * di;
        float w2 = dinv[s2] * di, w3 = dinv[s3] * di;
        uint4 u0 = *(const uint4*)(h + (size_t)s0 * D + lane * 8);
        uint4 u1 = *(const uint4*)(h + (size_t)s1 * D + lane * 8);
        uint4 u2 = *(const uint4*)(h + (size_t)s2 * D + lane * 8);
        uint4 u3 = *(const uint4*)(h + (size_t)s3 * D + lane * 8);
        float f0[8], f1[8], f2[8], f3[8];
        bf8_to_f(u0, f0);
        bf8_to_f(u1, f1);
        bf8_to_f(u2, f2);
        bf8_to_f(u3, f3);
#pragma unroll
        for (int j = 0; j < 8; j++)
            acc[j] += f0[j] * w0 + f1[j] * w1 + f2[j] * w2 + f3[j] * w3;
    }
    for (; e < e1; e++) {
        int s0 = csr_src[e];
        float w0 = dinv[s0] * di;
        uint4 u0 = *(const uint4*)(h + (size_t)s0 * D + lane * 8);
        bf8_to_f(u0, f);
#pragma unroll
        for (int j = 0; j < 8; j++) acc[j] += f[j] * w0;
    }

    // + bias
    {
        float4 b0 = ((const float4*)bias)[2 * lane];
        float4 b1 = ((const float4*)bias)[2 * lane + 1];
        acc[0] += b0.x; acc[1] += b0.y; acc[2] += b0.z; acc[3] += b0.w;
        acc[4] += b1.x; acc[5] += b1.y; acc[6] += b1.z; acc[7] += b1.w;
    }

    // LayerNorm
    float s = 0.f;
#pragma unroll
    for (int j = 0; j < 8; j++) s += acc[j];
#pragma unroll
    for (int o = 16; o > 0; o >>= 1) s += __shfl_xor_sync(0xffffffffu, s, o);
    float mu = s * (1.0f / D);

    float q = 0.f;
#pragma unroll
    for (int j = 0; j < 8; j++) {
        acc[j] -= mu;
        q += acc[j] * acc[j];
    }
#pragma unroll
    for (int o = 16; o > 0; o >>= 1) q += __shfl_xor_sync(0xffffffffu, q, o);
    float inv = rsqrtf(q * (1.0f / D) + LN_EPS);

    float4 w0 = ((const float4*)lw)[2 * lane];
    float4 w1 = ((const float4*)lw)[2 * lane + 1];
    float4 l0 = ((const float4*)lb)[2 * lane];
    float4 l1 = ((const float4*)lb)[2 * lane + 1];
    float wv[8] = {w0.x, w0.y, w0.z, w0.w, w1.x, w1.y, w1.z, w1.w};
    float lv[8] = {l0.x, l0.y, l0.z, l0.w, l1.x, l1.y, l1.z, l1.w};

    float o8[8];
#pragma unroll
    for (int j = 0; j < 8; j++)
        o8[j] = fmaxf(acc[j] * inv * wv[j] + lv[j], 0.f);

    if (SPLIT) {
        __nv_bfloat16 hh[8], ll[8];
#pragma unroll
        for (int j = 0; j < 8; j++) split_bf(o8[j], hh[j], ll[j]);
        uint4 uh, ul;
        __nv_bfloat162* ph = (__nv_bfloat162*)&uh;
        __nv_bfloat162* pl = (__nv_bfloat162*)&ul;
#pragma unroll
        for (int i = 0; i < 4; i++) {
            ph[i] = __nv_bfloat162(hh[2 * i], hh[2 * i + 1]);
            pl[i] = __nv_bfloat162(ll[2 * i], ll[2 * i + 1]);
        }
        *(uint4*)(out_h + (size_t)row * D + lane * 8) = uh;
        *(uint4*)(out_l + (size_t)row * D + lane * 8) = ul;
    } else {
        // final layer: bf16 activations only
        uint4 uh;
        __nv_bfloat162* ph = (__nv_bfloat162*)&uh;
#pragma unroll
        for (int i = 0; i < 4; i++)
            ph[i] = __floats2bfloat162_rn(o8[2 * i], o8[2 * i + 1]);
        *(uint4*)(out_h + (size_t)row * D + lane * 8) = uh;
    }
}

// ---------------- fused pool + head (batch is sorted, bf16 input) -------------
__device__ __forceinline__ int lower_bound_dev(const int* a, int n, int key) {
    int lo = 0, hi = n;
    while (lo < hi) {
        int mid = (lo + hi) >> 1;
        if (a[mid] < key) lo = mid + 1; else hi = mid;
    }
    return lo;
}

__global__ void pool_head_kernel(const int* __restrict__ batch,
                                 const __nv_bfloat16* __restrict__ h,
                                 const float* __restrict__ linW,
                                 const float* __restrict__ linb,
                                 float* __restrict__ out) {
    __shared__ float row[D];
    __shared__ int s_start, s_end;
    int g = blockIdx.x;
    int c = threadIdx.x;
    if (c == 0) {
        s_start = lower_bound_dev(batch, N_NODES, g);
        s_end   = lower_bound_dev(batch, N_NODES, g + 1);
    }
    __syncthreads();
    int start = s_start, end = s_end;
    float sum = 0.0f;
    for (int n = start; n < end; n++)
        sum += __bfloat162float(h[(size_t)n * D + c]);
    float cnt = (float)(end - start);
    row[c] = sum / fmaxf(cnt, 1.0f);
    __syncthreads();
    if (c < NC) {
        float acc = linb[c];
#pragma unroll 8
        for (int k = 0; k < D; k++) acc += row[k] * linW[k * NC + c];
        out[g * NC + c] = acc;
    }
}

// ---------------- launch ----------------
extern "C" void kernel_launch(void* const* d_in, const int* in_sizes, int n_in,
                              void* d_out, int out_size) {
    const float* x     = (const float*)d_in[0];
    const int*   ei    = (const int*)d_in[1];
    const int*   batch = (const int*)d_in[2];
    const float* W1    = (const float*)d_in[3];
    const float* b1    = (const float*)d_in[4];
    const float* W2    = (const float*)d_in[5];
    const float* b2    = (const float*)d_in[6];
    const float* ln1w  = (const float*)d_in[7];
    const float* ln1b  = (const float*)d_in[8];
    const float* ln2w  = (const float*)d_in[9];
    const float* ln2b  = (const float*)d_in[10];
    const float* linW  = (const float*)d_in[11];
    const float* linb  = (const float*)d_in[12];
    float* out = (float*)d_out;

    const int* src = ei;
    const int* dst = ei + N_EDGES;

    float *dinv;
    __nv_bfloat16 *Abf, *Bbf, *XH, *XL, *w1h, *w1l, *w2h, *w2l;
    int *counts, *offsets, *cursor, *csr_src, *bsums;
    cudaGetSymbolAddress((void**)&Abf,     g_Abf);
    cudaGetSymbolAddress((void**)&Bbf,     g_Bbf);
    cudaGetSymbolAddress((void**)&XH,      g_xh);
    cudaGetSymbolAddress((void**)&XL,      g_xl);
    cudaGetSymbolAddress((void**)&w1h,     g_w1h);
    cudaGetSymbolAddress((void**)&w1l,     g_w1l);
    cudaGetSymbolAddress((void**)&w2h,     g_w2h);
    cudaGetSymbolAddress((void**)&w2l,     g_w2l);
    cudaGetSymbolAddress((void**)&dinv,    g_dinv);
    cudaGetSymbolAddress((void**)&counts,  g_counts);
    cudaGetSymbolAddress((void**)&offsets, g_offsets);
    cudaGetSymbolAddress((void**)&cursor,  g_cursor);
    cudaGetSymbolAddress((void**)&bsums,   g_bsums);
    cudaGetSymbolAddress((void**)&csr_src, g_csr_src);

    cudaFuncSetAttribute(gemm_bf16_kernel,
                         cudaFuncAttributeMaxDynamicSharedMemorySize, GEMM_SMEM);

    // prep (also zeroes counts) + weights
    prep_x_kernel<<<(N_NODES * (D / 4) + 255) / 256, 256>>>(x, XH, XL, counts);
    prep_w_kernel<<<2 * D, D>>>(W1, W2, w1h, w1l, w2h, w2l);

    // CSR build
    deg_count_kernel<<<(N_EDGES + 255) / 256, 256>>>(dst, counts);
    scan_blocksum_kernel<<<SCAN_NB, SCAN_BLK>>>(counts, bsums);
    scan_sums_kernel<<<1, 128>>>(bsums);
    scan_local_kernel<<<SCAN_NB, SCAN_BLK>>>(counts, bsums, offsets, cursor, dinv);
    fill_kernel<<<(N_EDGES + 255) / 256, 256>>>(src, dst, cursor, csr_src);

    dim3 ggrid(2, (N_NODES + 127) / 128);

    // layer 1
    gemm_bf16_kernel<<<ggrid, 256, GEMM_SMEM>>>(XH, XL, w1h, w1l, Abf);
    agg_ln_kernel<true><<<(N_NODES + 7) / 8, 256>>>(Abf, offsets, csr_src, dinv,
                                                    b1, ln1w, ln1b, XH, XL);
    // layer 2
    gemm_bf16_kernel<<<ggrid, 256, GEMM_SMEM>>>(XH, XL, w2h, w2l, Abf);
    agg_ln_kernel<false><<<(N_NODES + 7) / 8, 256>>>(Abf, offsets, csr_src, dinv,
                                                     b2, ln2w, ln2b, Bbf, nullptr);

    // pool + head
    pool_head_kernel<<<NG, D>>>(batch, Bbf, linW, linb, out);
}